// round 15
// baseline (speedup 1.0000x reference)
#include <cuda_runtime.h>
#include <cstdint>

// ---------------------------------------------------------------------------
// PointNet++ decoder. Conv1x1 GEMMs on fp32 pipe via Blackwell packed
// fma.rn.f32x2 (FFMA2). Occupancy fix: __launch_bounds__(256,3) + split-K so
// every GEMM grid has >= ~450 CTAs (3 CTAs/SM -> 24 warps hides LDS latency).
// Split-K writes private partial slices (deterministic), combined by a kernel
// that also produces the BN stats. Target sm_100: no tcgen05 / kind::tf32.
// ---------------------------------------------------------------------------

#define B_SZ 8
#define N0 8192
#define N1 2048
#define N2 512
#define N3 128

__device__ float g_big[192 * (B_SZ * N0)];   // X0; later aliased as Y01
__device__ float g_Y00[128 * (B_SZ * N0)];   // FP0 conv0 out; ALSO split-K partials
__device__ float g_X2[768 * (B_SZ * N2)];
__device__ float g_Y20[256 * (B_SZ * N2)];
__device__ float g_F2N[256 * (B_SZ * N2)];
__device__ float g_X1[384 * (B_SZ * N1)];
__device__ float g_Y10[256 * (B_SZ * N1)];
__device__ float g_F1N[128 * (B_SZ * N1)];
__device__ float g_sums[6 * 512];  // per layer: [0,256)=sum, [256,512)=sumsq

// ---------------- packed f32x2 helpers ----------------
__device__ __forceinline__ unsigned long long pack2(float x, float y) {
    unsigned long long r;
    asm("mov.b64 %0, {%1, %2};" : "=l"(r) : "f"(x), "f"(y));
    return r;
}
__device__ __forceinline__ unsigned long long fma2(unsigned long long a,
                                                   unsigned long long b,
                                                   unsigned long long c) {
    unsigned long long d;
    asm("fma.rn.f32x2 %0, %1, %2, %3;" : "=l"(d) : "l"(a), "l"(b), "l"(c));
    return d;
}

// ---------------------------------------------------------------------------
// copy skip features (B,C,N) -> X rows [0,C), layout (C, B*N)
// ---------------------------------------------------------------------------
__global__ void copy_skip_kernel(const float* __restrict__ src,
                                 float* __restrict__ dst,
                                 int B, int C, int N) {
    size_t t = ((size_t)blockIdx.x * blockDim.x + threadIdx.x) * 4;
    int BN = B * N;
    int c = (int)(t / BN);
    int rem = (int)(t % BN);
    int b = rem / N;
    int n = rem % N;
    *(float4*)(dst + t) =
        *(const float4*)(src + ((size_t)b * C + c) * N + n);
}

// ---------------------------------------------------------------------------
// kNN(3) + inverse-distance interpolation (channel-major feats).
// ---------------------------------------------------------------------------
__global__ void knn_interp_kernel(const float* __restrict__ uxyz,
                                  const float* __restrict__ kxyz,
                                  const float* __restrict__ feats,
                                  float* __restrict__ X,
                                  int n, int m, int C, int c0,
                                  int fb, int fc, int B) {
    __shared__ float skx[2048];
    __shared__ float sky[2048];
    __shared__ float skz[2048];

    const int b = blockIdx.y;
    const int pi = blockIdx.x * blockDim.x + threadIdx.x;

    for (int j = threadIdx.x; j < m; j += blockDim.x) {
        const float* p = kxyz + ((size_t)b * m + j) * 3;
        skx[j] = p[0];
        sky[j] = p[1];
        skz[j] = p[2];
    }
    __syncthreads();
    if (pi >= n) return;

    const float* up = uxyz + ((size_t)b * n + pi) * 3;
    const float ux = up[0], uy = up[1], uz = up[2];

    float d0 = 1e30f, d1 = 1e30f, d2 = 1e30f;
    int i0 = 0, i1 = 0, i2 = 0;
    for (int j = 0; j < m; ++j) {
        float dx = ux - skx[j];
        float dy = uy - sky[j];
        float dz = uz - skz[j];
        float d = dx * dx + dy * dy + dz * dz;
        if (d < d2) {
            if (d < d1) {
                d2 = d1; i2 = i1;
                if (d < d0) { d1 = d0; i1 = i0; d0 = d; i0 = j; }
                else        { d1 = d;  i1 = j; }
            } else {
                d2 = d; i2 = j;
            }
        }
    }

    float r0 = 1.0f / (d0 + 1e-8f);
    float r1 = 1.0f / (d1 + 1e-8f);
    float r2 = 1.0f / (d2 + 1e-8f);
    float rs = 1.0f / (r0 + r1 + r2);
    const float w0 = r0 * rs, w1 = r1 * rs, w2 = r2 * rs;

    const float* fbase = feats + (size_t)b * fb;
    const size_t ocol = (size_t)b * n + pi;
    const size_t rowstride = (size_t)B * n;
    float* outp = X + (size_t)c0 * rowstride + ocol;
    for (int c = 0; c < C; ++c) {
        const float* fr = fbase + (size_t)c * fc;
        outp[(size_t)c * rowstride] = w0 * fr[i0] + w1 * fr[i1] + w2 * fr[i2];
    }
}

// ---------------------------------------------------------------------------
// SGEMM with packed f32x2 FMA. C(M x N) = A(M x K) @ B(K x N), row-major.
// CTA tile 128 x BN x 16, 256 threads, micro-tile 8 x (2*NP).
// KSPLIT > 1: blockIdx.z handles K-range [z*K/KSPLIT, ...); output goes to
// its own partial slice C + z*M*N (combined later). Deterministic.
// ---------------------------------------------------------------------------
template <int BN, int NP, int KSPLIT>
__global__ __launch_bounds__(256, 3) void sgemm_f32x2_kernel(
    const float* __restrict__ A, const float* __restrict__ Bm,
    float* __restrict__ C, int M, int N, int K) {
    __shared__ float As[16][128];  // As[k][m]
    __shared__ float Bs[16][BN];   // Bs[k][n]

    const int tid = threadIdx.x;
    const int bm = blockIdx.y * 128;
    const int bn = blockIdx.x * BN;
    const int tx = tid & 15;
    const int ty = tid >> 4;

    const int kchunk = K / KSPLIT;
    const int kbeg = (KSPLIT > 1) ? blockIdx.z * kchunk : 0;
    if (KSPLIT > 1) C += (size_t)blockIdx.z * M * N;

    // A loaders: 512 float4/tile; thread t -> {t, t+256}
    const int a_row = tid & 127;
    const int a_c0 = (tid >> 7) * 4;  // 0 or 4
    const float* Ap0 = A + (size_t)(bm + a_row) * K + kbeg + a_c0;
    const float* Ap1 = Ap0 + 8;

    int b_k0, b_col;
    if (BN == 128) { b_k0 = tid >> 5; b_col = (tid & 31) * 4; }
    else           { b_k0 = tid >> 4; b_col = (tid & 15) * 4; }
    const float* Bp0 = Bm + (size_t)(kbeg + b_k0) * N + bn + b_col;
    const float* Bp1 = Bp0 + (size_t)8 * N;  // only when BN == 128

    unsigned long long acc[8][NP];
#pragma unroll
    for (int i = 0; i < 8; ++i)
#pragma unroll
        for (int j = 0; j < NP; ++j) acc[i][j] = 0ull;

    float4 pa0 = *(const float4*)(Ap0);
    float4 pa1 = *(const float4*)(Ap1);
    float4 pb0 = *(const float4*)(Bp0);
    float4 pb1;
    if (BN == 128) pb1 = *(const float4*)(Bp1);

    for (int k0 = 0; k0 < kchunk; k0 += 16) {
        As[a_c0 + 0][a_row] = pa0.x;
        As[a_c0 + 1][a_row] = pa0.y;
        As[a_c0 + 2][a_row] = pa0.z;
        As[a_c0 + 3][a_row] = pa0.w;
        As[a_c0 + 8][a_row] = pa1.x;
        As[a_c0 + 9][a_row] = pa1.y;
        As[a_c0 + 10][a_row] = pa1.z;
        As[a_c0 + 11][a_row] = pa1.w;
        *(float4*)&Bs[b_k0][b_col] = pb0;
        if (BN == 128) *(float4*)&Bs[b_k0 + 8][b_col] = pb1;
        __syncthreads();

        if (k0 + 16 < kchunk) {
            pa0 = *(const float4*)(Ap0 + k0 + 16);
            pa1 = *(const float4*)(Ap1 + k0 + 16);
            pb0 = *(const float4*)(Bp0 + (size_t)(k0 + 16) * N);
            if (BN == 128) pb1 = *(const float4*)(Bp1 + (size_t)(k0 + 16) * N);
        }

#pragma unroll
        for (int kk = 0; kk < 16; ++kk) {
            float af[8];
            *(float4*)&af[0] = *(const float4*)&As[kk][ty * 4];
            *(float4*)&af[4] = *(const float4*)&As[kk][ty * 4 + 64];
            unsigned long long bp[NP];
            {
                ulonglong2 t0 = *(const ulonglong2*)&Bs[kk][tx * 4];
                bp[0] = t0.x; bp[1] = t0.y;
                if (BN == 128) {
                    ulonglong2 t1 = *(const ulonglong2*)&Bs[kk][tx * 4 + 64];
                    bp[2] = t1.x; bp[3] = t1.y;
                }
            }
#pragma unroll
            for (int i = 0; i < 8; ++i) {
                unsigned long long aa = pack2(af[i], af[i]);
#pragma unroll
                for (int j = 0; j < NP; ++j)
                    acc[i][j] = fma2(aa, bp[j], acc[i][j]);
            }
        }
        __syncthreads();
    }

#pragma unroll
    for (int ih = 0; ih < 2; ++ih) {
#pragma unroll
        for (int i = 0; i < 4; ++i) {
            const int row = bm + ih * 64 + ty * 4 + i;
            float* cp = C + (size_t)row * N + bn;
            ulonglong2 v0;
            v0.x = acc[ih * 4 + i][0];
            v0.y = acc[ih * 4 + i][1];
            *(ulonglong2*)(cp + tx * 4) = v0;
            if (BN == 128) {
                ulonglong2 v1;
                v1.x = acc[ih * 4 + i][2];
                v1.y = acc[ih * 4 + i][3];
                *(ulonglong2*)(cp + tx * 4 + 64) = v1;
            }
        }
    }
}

// ---------------------------------------------------------------------------
// zero sums
// ---------------------------------------------------------------------------
__global__ void zero_sums_kernel(float* sums) {
    sums[blockIdx.x * 256 + threadIdx.x] = 0.0f;
}

// ---------------------------------------------------------------------------
// Split-K combine + BN stats: Y = sum of ksplit partial slices; accumulates
// per-channel {sum, sumsq} via atomics. grid (C, nchunk), block 256.
// ---------------------------------------------------------------------------
__global__ void combine_stats_kernel(const float* __restrict__ part,
                                     float* __restrict__ Y,
                                     float* __restrict__ sums,
                                     int Ncols, int MN, int ksplit) {
    const int c = blockIdx.x;
    const int len = Ncols / gridDim.y;
    const size_t off = (size_t)c * Ncols + (size_t)blockIdx.y * len;
    float s = 0.0f, s2 = 0.0f;
    for (int i = threadIdx.x * 4; i < len; i += blockDim.x * 4) {
        float4 a = *(const float4*)(part + off + i);
        for (int sp = 1; sp < ksplit; ++sp) {
            float4 w = *(const float4*)(part + (size_t)sp * MN + off + i);
            a.x += w.x; a.y += w.y; a.z += w.z; a.w += w.w;
        }
        *(float4*)(Y + off + i) = a;
        s += a.x + a.y + a.z + a.w;
        s2 += a.x * a.x + a.y * a.y + a.z * a.z + a.w * a.w;
    }
#pragma unroll
    for (int o = 16; o; o >>= 1) {
        s += __shfl_down_sync(0xFFFFFFFFu, s, o);
        s2 += __shfl_down_sync(0xFFFFFFFFu, s2, o);
    }
    __shared__ float ws[8], ws2[8];
    const int w = threadIdx.x >> 5, l = threadIdx.x & 31;
    if (l == 0) { ws[w] = s; ws2[w] = s2; }
    __syncthreads();
    if (threadIdx.x == 0) {
        float S = 0.0f, S2 = 0.0f;
        const int nw = blockDim.x >> 5;
        for (int i = 0; i < nw; ++i) { S += ws[i]; S2 += ws2[i]; }
        atomicAdd(&sums[c], S);
        atomicAdd(&sums[256 + c], S2);
    }
}

// ---------------------------------------------------------------------------
// BN stats (no split): grid (C, nchunk); atomicAdd partial {sum, sumsq}.
// ---------------------------------------------------------------------------
__global__ void bn_stats_part_kernel(const float* __restrict__ Y,
                                     float* __restrict__ sums, int Ncols) {
    const int c = blockIdx.x;
    const int len = Ncols / gridDim.y;
    const float* row = Y + (size_t)c * Ncols + (size_t)blockIdx.y * len;
    float s = 0.0f, s2 = 0.0f;
    for (int i = threadIdx.x * 4; i < len; i += blockDim.x * 4) {
        float4 v = *(const float4*)(row + i);
        s += v.x + v.y + v.z + v.w;
        s2 += v.x * v.x + v.y * v.y + v.z * v.z + v.w * v.w;
    }
#pragma unroll
    for (int o = 16; o; o >>= 1) {
        s += __shfl_down_sync(0xFFFFFFFFu, s, o);
        s2 += __shfl_down_sync(0xFFFFFFFFu, s2, o);
    }
    __shared__ float ws[8], ws2[8];
    const int w = threadIdx.x >> 5, l = threadIdx.x & 31;
    if (l == 0) { ws[w] = s; ws2[w] = s2; }
    __syncthreads();
    if (threadIdx.x == 0) {
        float S = 0.0f, S2 = 0.0f;
        const int nw = blockDim.x >> 5;
        for (int i = 0; i < nw; ++i) { S += ws[i]; S2 += ws2[i]; }
        atomicAdd(&sums[c], S);
        atomicAdd(&sums[256 + c], S2);
    }
}

// ---------------------------------------------------------------------------
// BN apply + ReLU, in place on (C x Ncols); mean/rstd from raw sums
// ---------------------------------------------------------------------------
__global__ void bn_apply_ip_kernel(float* __restrict__ Y,
                                   const float* __restrict__ sums,
                                   const float* __restrict__ gamma,
                                   const float* __restrict__ beta,
                                   int Ncols, float invN) {
    size_t t = ((size_t)blockIdx.x * blockDim.x + threadIdx.x) * 4;
    const int c = (int)(t / Ncols);
    const float mean = sums[c] * invN;
    const float var = sums[256 + c] * invN - mean * mean;
    const float g = gamma[c] * rsqrtf(var + 1e-5f);
    const float b = beta[c] - mean * g;
    float4 v = *(float4*)(Y + t);
    v.x = fmaxf(v.x * g + b, 0.0f);
    v.y = fmaxf(v.y * g + b, 0.0f);
    v.z = fmaxf(v.z * g + b, 0.0f);
    v.w = fmaxf(v.w * g + b, 0.0f);
    *(float4*)(Y + t) = v;
}

// ---------------------------------------------------------------------------
// BN apply + ReLU, (C, B*N) -> out (B,C,N)
// ---------------------------------------------------------------------------
__global__ void bn_apply_out_kernel(const float* __restrict__ Y,
                                    const float* __restrict__ sums,
                                    const float* __restrict__ gamma,
                                    const float* __restrict__ beta,
                                    float* __restrict__ out,
                                    int B, int C, int N, float invN) {
    size_t t = ((size_t)blockIdx.x * blockDim.x + threadIdx.x) * 4;
    const int BN = B * N;
    const int c = (int)(t / BN);
    const int rem = (int)(t % BN);
    const int b = rem / N;
    const int n = rem % N;
    const float mean = sums[c] * invN;
    const float var = sums[256 + c] * invN - mean * mean;
    const float g = gamma[c] * rsqrtf(var + 1e-5f);
    const float bb = beta[c] - mean * g;
    float4 v = *(const float4*)(Y + t);
    v.x = fmaxf(v.x * g + bb, 0.0f);
    v.y = fmaxf(v.y * g + bb, 0.0f);
    v.z = fmaxf(v.z * g + bb, 0.0f);
    v.w = fmaxf(v.w * g + bb, 0.0f);
    *(float4*)(out + ((size_t)b * C + c) * N + n) = v;
}

// ---------------------------------------------------------------------------
// host driver
// ---------------------------------------------------------------------------
extern "C" void kernel_launch(void* const* d_in, const int* in_sizes, int n_in,
                              void* d_out, int out_size) {
    const float* in[26];
    for (int i = 0; i < 26 && i < n_in; ++i) in[i] = (const float*)d_in[i];

    const float *xyz0, *xyz1, *xyz2, *xyz3, *f0, *f1, *f2, *f3;
    if (in_sizes[1] == 8 * 64 * 8192) {  // interleaved: xyz0,f0,xyz1,f1,...
        xyz0 = in[0]; f0 = in[1]; xyz1 = in[2]; f1 = in[3];
        xyz2 = in[4]; f2 = in[5]; xyz3 = in[6]; f3 = in[7];
    } else {  // grouped
        xyz0 = in[0]; xyz1 = in[1]; xyz2 = in[2]; xyz3 = in[3];
        f0 = in[4]; f1 = in[5]; f2 = in[6]; f3 = in[7];
    }
    const float *w00 = in[8],  *g00 = in[9],  *b00 = in[10];
    const float *w01 = in[11], *g01 = in[12], *b01 = in[13];
    const float *w10 = in[14], *g10 = in[15], *b10 = in[16];
    const float *w11 = in[17], *g11 = in[18], *b11 = in[19];
    const float *w20 = in[20], *g20 = in[21], *b20 = in[22];
    const float *w21 = in[23], *g21 = in[24], *b21 = in[25];

    float *big, *Y00, *X2, *Y20, *F2N, *X1, *Y10, *F1N, *sums;
    cudaGetSymbolAddress((void**)&big, g_big);
    cudaGetSymbolAddress((void**)&Y00, g_Y00);
    cudaGetSymbolAddress((void**)&X2, g_X2);
    cudaGetSymbolAddress((void**)&Y20, g_Y20);
    cudaGetSymbolAddress((void**)&F2N, g_F2N);
    cudaGetSymbolAddress((void**)&X1, g_X1);
    cudaGetSymbolAddress((void**)&Y10, g_Y10);
    cudaGetSymbolAddress((void**)&F1N, g_F1N);
    cudaGetSymbolAddress((void**)&sums, g_sums);

    float* X0   = big;   // 192 x 65536 during FP0 concat + conv0
    float* Y01  = big;   // 128 x 65536 after conv0 (X0 dead: conv1 reads Y00)
    float* part = Y00;   // split-K partials (8.39M floats); Y00 live only in FP0

    float* out = (float*)d_out;
    const int B = B_SZ;

    zero_sums_kernel<<<12, 256>>>(sums);

    // ---------------- FP2: xyz2 (n=512) <- xyz3 (m=128) ----------------
    {
        const int n = N2, m = N3, Cskip = 256, Cf = 512, cols = B * n;  // 4096
        copy_skip_kernel<<<(B * Cskip * n) / 1024, 256>>>(f2, X2, B, Cskip, n);
        knn_interp_kernel<<<dim3(n / 256, B), 256>>>(
            xyz2, xyz3, f3, X2, n, m, Cf, Cskip, /*fb=*/Cf * m, /*fc=*/m, B);

        // conv0: M=256, N=4096, K=768, BN=64, KSPLIT=6 -> grid 768
        sgemm_f32x2_kernel<64, 2, 6><<<dim3(cols / 64, 2, 6), 256>>>(
            w20, X2, part, 256, cols, 768);
        combine_stats_kernel<<<dim3(256, 4), 256>>>(part, Y20, sums + 0 * 512,
                                                    cols, 256 * cols, 6);
        bn_apply_ip_kernel<<<256 * cols / 1024, 256>>>(
            Y20, sums + 0 * 512, g20, b20, cols, 1.0f / (float)cols);

        // conv1: M=256, N=4096, K=256, BN=64, KSPLIT=4 -> grid 512
        sgemm_f32x2_kernel<64, 2, 4><<<dim3(cols / 64, 2, 4), 256>>>(
            w21, Y20, part, 256, cols, 256);
        combine_stats_kernel<<<dim3(256, 4), 256>>>(part, F2N, sums + 1 * 512,
                                                    cols, 256 * cols, 4);
        bn_apply_ip_kernel<<<256 * cols / 1024, 256>>>(
            F2N, sums + 1 * 512, g21, b21, cols, 1.0f / (float)cols);
    }

    // ---------------- FP1: xyz1 (n=2048) <- xyz2 (m=512) ----------------
    {
        const int n = N1, m = N2, Cskip = 128, Cf = 256, cols = B * n;  // 16384
        copy_skip_kernel<<<(B * Cskip * n) / 1024, 256>>>(f1, X1, B, Cskip, n);
        knn_interp_kernel<<<dim3(n / 256, B), 256>>>(
            xyz1, xyz2, F2N, X1, n, m, Cf, Cskip, /*fb=*/m, /*fc=*/B * m, B);

        // conv0: M=256, N=16384, K=384, BN=128, KSPLIT=2 -> grid 512
        sgemm_f32x2_kernel<128, 4, 2><<<dim3(cols / 128, 2, 2), 256>>>(
            w10, X1, part, 256, cols, 384);
        combine_stats_kernel<<<dim3(256, 16), 256>>>(part, Y10, sums + 2 * 512,
                                                     cols, 256 * cols, 2);
        bn_apply_ip_kernel<<<256 * cols / 1024, 256>>>(
            Y10, sums + 2 * 512, g10, b10, cols, 1.0f / (float)cols);

        // conv1: M=128, N=16384, K=256, BN=128, KSPLIT=4 -> grid 512
        sgemm_f32x2_kernel<128, 4, 4><<<dim3(cols / 128, 1, 4), 256>>>(
            w11, Y10, part, 128, cols, 256);
        combine_stats_kernel<<<dim3(128, 16), 256>>>(part, F1N, sums + 3 * 512,
                                                     cols, 128 * cols, 4);
        bn_apply_ip_kernel<<<128 * cols / 1024, 256>>>(
            F1N, sums + 3 * 512, g11, b11, cols, 1.0f / (float)cols);
    }

    // ---------------- FP0: xyz0 (n=8192) <- xyz1 (m=2048) ----------------
    {
        const int n = N0, m = N1, Cskip = 64, Cf = 128, cols = B * n;  // 65536
        copy_skip_kernel<<<(B * Cskip * n) / 1024, 256>>>(f0, X0, B, Cskip, n);
        knn_interp_kernel<<<dim3(n / 256, B), 256>>>(
            xyz0, xyz1, F1N, X0, n, m, Cf, Cskip, /*fb=*/m, /*fc=*/B * m, B);

        // conv0: M=128, N=65536, K=192 -> grid 512 (no split)
        sgemm_f32x2_kernel<128, 4, 1><<<dim3(cols / 128, 1, 1), 256>>>(
            w00, X0, Y00, 128, cols, 192);
        bn_stats_part_kernel<<<dim3(128, 8), 256>>>(Y00, sums + 4 * 512, cols);
        bn_apply_ip_kernel<<<128 * cols / 1024, 256>>>(
            Y00, sums + 4 * 512, g00, b00, cols, 1.0f / (float)cols);

        // conv1: M=128, N=65536, K=128 -> grid 512 (no split)
        sgemm_f32x2_kernel<128, 4, 1><<<dim3(cols / 128, 1, 1), 256>>>(
            w01, Y00, Y01, 128, cols, 128);
        bn_stats_part_kernel<<<dim3(128, 8), 256>>>(Y01, sums + 5 * 512, cols);
        bn_apply_out_kernel<<<128 * cols / 1024, 256>>>(
            Y01, sums + 5 * 512, g01, b01, out, B, 128, n,
            1.0f / (float)cols);
    }
}

// round 16
// speedup vs baseline: 1.0158x; 1.0158x over previous
#include <cuda_runtime.h>
#include <cstdint>

// ---------------------------------------------------------------------------
// PointNet++ decoder. Conv1x1 GEMMs on fp32 pipe via Blackwell packed
// fma.rn.f32x2 (FFMA2). This round: double-buffered SMEM pipeline (one sync
// per K-tile; LDG prefetch overlaps compute) + no split-K (R15 showed the
// combine traffic costs more than it saves).
// Layout: X is (C_rows, B*N cols) row-major; convs are single GEMMs; BN stats
// are 8-way-split row reductions with atomics.
// Target sm_100 (no 'a'): no tcgen05, no kind::tf32.
// ---------------------------------------------------------------------------

#define B_SZ 8
#define N0 8192
#define N1 2048
#define N2 512
#define N3 128

__device__ float g_big[192 * (B_SZ * N0)];   // X0; later aliased as Y01
__device__ float g_Y00[128 * (B_SZ * N0)];
__device__ float g_X2[768 * (B_SZ * N2)];
__device__ float g_Y20[256 * (B_SZ * N2)];
__device__ float g_F2N[256 * (B_SZ * N2)];
__device__ float g_X1[384 * (B_SZ * N1)];
__device__ float g_Y10[256 * (B_SZ * N1)];
__device__ float g_F1N[128 * (B_SZ * N1)];
__device__ float g_sums[6 * 512];  // per layer: [0,256)=sum, [256,512)=sumsq

// ---------------- packed f32x2 helpers ----------------
__device__ __forceinline__ unsigned long long pack2(float x, float y) {
    unsigned long long r;
    asm("mov.b64 %0, {%1, %2};" : "=l"(r) : "f"(x), "f"(y));
    return r;
}
__device__ __forceinline__ unsigned long long fma2(unsigned long long a,
                                                   unsigned long long b,
                                                   unsigned long long c) {
    unsigned long long d;
    asm("fma.rn.f32x2 %0, %1, %2, %3;" : "=l"(d) : "l"(a), "l"(b), "l"(c));
    return d;
}

// ---------------------------------------------------------------------------
// copy skip features (B,C,N) -> X rows [0,C), layout (C, B*N)
// ---------------------------------------------------------------------------
__global__ void copy_skip_kernel(const float* __restrict__ src,
                                 float* __restrict__ dst,
                                 int B, int C, int N) {
    size_t t = ((size_t)blockIdx.x * blockDim.x + threadIdx.x) * 4;
    int BN = B * N;
    int c = (int)(t / BN);
    int rem = (int)(t % BN);
    int b = rem / N;
    int n = rem % N;
    *(float4*)(dst + t) =
        *(const float4*)(src + ((size_t)b * C + c) * N + n);
}

// ---------------------------------------------------------------------------
// kNN(3) + inverse-distance interpolation (channel-major feats).
// ---------------------------------------------------------------------------
__global__ void knn_interp_kernel(const float* __restrict__ uxyz,
                                  const float* __restrict__ kxyz,
                                  const float* __restrict__ feats,
                                  float* __restrict__ X,
                                  int n, int m, int C, int c0,
                                  int fb, int fc, int B) {
    __shared__ float skx[2048];
    __shared__ float sky[2048];
    __shared__ float skz[2048];

    const int b = blockIdx.y;
    const int pi = blockIdx.x * blockDim.x + threadIdx.x;

    for (int j = threadIdx.x; j < m; j += blockDim.x) {
        const float* p = kxyz + ((size_t)b * m + j) * 3;
        skx[j] = p[0];
        sky[j] = p[1];
        skz[j] = p[2];
    }
    __syncthreads();
    if (pi >= n) return;

    const float* up = uxyz + ((size_t)b * n + pi) * 3;
    const float ux = up[0], uy = up[1], uz = up[2];

    float d0 = 1e30f, d1 = 1e30f, d2 = 1e30f;
    int i0 = 0, i1 = 0, i2 = 0;
    for (int j = 0; j < m; ++j) {
        float dx = ux - skx[j];
        float dy = uy - sky[j];
        float dz = uz - skz[j];
        float d = dx * dx + dy * dy + dz * dz;
        if (d < d2) {
            if (d < d1) {
                d2 = d1; i2 = i1;
                if (d < d0) { d1 = d0; i1 = i0; d0 = d; i0 = j; }
                else        { d1 = d;  i1 = j; }
            } else {
                d2 = d; i2 = j;
            }
        }
    }

    float r0 = 1.0f / (d0 + 1e-8f);
    float r1 = 1.0f / (d1 + 1e-8f);
    float r2 = 1.0f / (d2 + 1e-8f);
    float rs = 1.0f / (r0 + r1 + r2);
    const float w0 = r0 * rs, w1 = r1 * rs, w2 = r2 * rs;

    const float* fbase = feats + (size_t)b * fb;
    const size_t ocol = (size_t)b * n + pi;
    const size_t rowstride = (size_t)B * n;
    float* outp = X + (size_t)c0 * rowstride + ocol;
    for (int c = 0; c < C; ++c) {
        const float* fr = fbase + (size_t)c * fc;
        outp[(size_t)c * rowstride] = w0 * fr[i0] + w1 * fr[i1] + w2 * fr[i2];
    }
}

// ---------------------------------------------------------------------------
// Double-buffered SGEMM with packed f32x2 FMA.
// C(M x N) = A(M x K) @ B(K x N), row-major. CTA tile 128 x BN x 16,
// 256 threads, micro-tile 8 x (2*NP). 2-stage SMEM: one __syncthreads per
// K-tile; global prefetch issued before compute, stored after.
// M in {128,256}, N % BN == 0, K % 16 == 0 (exact for this problem).
// ---------------------------------------------------------------------------
template <int BN, int NP>
__global__ __launch_bounds__(256, 3) void sgemm_db_kernel(
    const float* __restrict__ A, const float* __restrict__ Bm,
    float* __restrict__ C, int M, int N, int K) {
    __shared__ float As[2][16][128];  // As[buf][k][m]
    __shared__ float Bs[2][16][BN];   // Bs[buf][k][n]

    const int tid = threadIdx.x;
    const int bm = blockIdx.y * 128;
    const int bn = blockIdx.x * BN;
    const int tx = tid & 15;
    const int ty = tid >> 4;

    // A loaders: 512 float4/tile; thread t -> rows (t&127), col-halves
    const int a_row = tid & 127;
    const int a_c0 = (tid >> 7) * 4;  // 0 or 4 (plus +8 for second load)
    const float* Ap0 = A + (size_t)(bm + a_row) * K + a_c0;
    const float* Ap1 = Ap0 + 8;

    int b_k0, b_col;
    if (BN == 128) { b_k0 = tid >> 5; b_col = (tid & 31) * 4; }  // rows k0,k0+8
    else           { b_k0 = tid >> 4; b_col = (tid & 15) * 4; }  // 1 row
    const float* Bp0 = Bm + (size_t)b_k0 * N + bn + b_col;
    const float* Bp1 = Bp0 + (size_t)8 * N;  // only when BN == 128

    unsigned long long acc[8][NP];
#pragma unroll
    for (int i = 0; i < 8; ++i)
#pragma unroll
        for (int j = 0; j < NP; ++j) acc[i][j] = 0ull;

    const int nt = K >> 4;  // number of 16-wide K tiles

    // ---- prologue: load tile 0 and stage into buffer 0 ----
    float4 pa0 = *(const float4*)(Ap0);
    float4 pa1 = *(const float4*)(Ap1);
    float4 pb0 = *(const float4*)(Bp0);
    float4 pb1;
    if (BN == 128) pb1 = *(const float4*)(Bp1);

    As[0][a_c0 + 0][a_row] = pa0.x;
    As[0][a_c0 + 1][a_row] = pa0.y;
    As[0][a_c0 + 2][a_row] = pa0.z;
    As[0][a_c0 + 3][a_row] = pa0.w;
    As[0][a_c0 + 8][a_row] = pa1.x;
    As[0][a_c0 + 9][a_row] = pa1.y;
    As[0][a_c0 + 10][a_row] = pa1.z;
    As[0][a_c0 + 11][a_row] = pa1.w;
    *(float4*)&Bs[0][b_k0][b_col] = pb0;
    if (BN == 128) *(float4*)&Bs[0][b_k0 + 8][b_col] = pb1;
    __syncthreads();

    for (int t = 0; t < nt; ++t) {
        const int cur = t & 1;
        const int nxt = cur ^ 1;
        const bool more = (t + 1) < nt;

        // issue global prefetch for tile t+1 (overlaps compute below)
        if (more) {
            const int ko = (t + 1) * 16;
            pa0 = *(const float4*)(Ap0 + ko);
            pa1 = *(const float4*)(Ap1 + ko);
            pb0 = *(const float4*)(Bp0 + (size_t)ko * N);
            if (BN == 128) pb1 = *(const float4*)(Bp1 + (size_t)ko * N);
        }

        // compute on buffer `cur`
#pragma unroll
        for (int kk = 0; kk < 16; ++kk) {
            float af[8];
            *(float4*)&af[0] = *(const float4*)&As[cur][kk][ty * 4];
            *(float4*)&af[4] = *(const float4*)&As[cur][kk][ty * 4 + 64];
            unsigned long long bp[NP];
            {
                ulonglong2 t0 = *(const ulonglong2*)&Bs[cur][kk][tx * 4];
                bp[0] = t0.x; bp[1] = t0.y;
                if (BN == 128) {
                    ulonglong2 t1 =
                        *(const ulonglong2*)&Bs[cur][kk][tx * 4 + 64];
                    bp[2] = t1.x; bp[3] = t1.y;
                }
            }
#pragma unroll
            for (int i = 0; i < 8; ++i) {
                unsigned long long aa = pack2(af[i], af[i]);
#pragma unroll
                for (int j = 0; j < NP; ++j)
                    acc[i][j] = fma2(aa, bp[j], acc[i][j]);
            }
        }

        // stage tile t+1 into buffer `nxt` (other warps may still compute cur)
        if (more) {
            As[nxt][a_c0 + 0][a_row] = pa0.x;
            As[nxt][a_c0 + 1][a_row] = pa0.y;
            As[nxt][a_c0 + 2][a_row] = pa0.z;
            As[nxt][a_c0 + 3][a_row] = pa0.w;
            As[nxt][a_c0 + 8][a_row] = pa1.x;
            As[nxt][a_c0 + 9][a_row] = pa1.y;
            As[nxt][a_c0 + 10][a_row] = pa1.z;
            As[nxt][a_c0 + 11][a_row] = pa1.w;
            *(float4*)&Bs[nxt][b_k0][b_col] = pb0;
            if (BN == 128) *(float4*)&Bs[nxt][b_k0 + 8][b_col] = pb1;
            __syncthreads();
        }
    }

    // ---- epilogue ----
#pragma unroll
    for (int ih = 0; ih < 2; ++ih) {
#pragma unroll
        for (int i = 0; i < 4; ++i) {
            const int row = bm + ih * 64 + ty * 4 + i;
            float* cp = C + (size_t)row * N + bn;
            ulonglong2 v0;
            v0.x = acc[ih * 4 + i][0];
            v0.y = acc[ih * 4 + i][1];
            *(ulonglong2*)(cp + tx * 4) = v0;
            if (BN == 128) {
                ulonglong2 v1;
                v1.x = acc[ih * 4 + i][2];
                v1.y = acc[ih * 4 + i][3];
                *(ulonglong2*)(cp + tx * 4 + 64) = v1;
            }
        }
    }
}

// ---------------------------------------------------------------------------
// zero sums
// ---------------------------------------------------------------------------
__global__ void zero_sums_kernel(float* sums) {
    sums[blockIdx.x * 256 + threadIdx.x] = 0.0f;
}

// ---------------------------------------------------------------------------
// BN stats: grid (C, nchunk); atomicAdd partial {sum, sumsq}.
// ---------------------------------------------------------------------------
__global__ void bn_stats_part_kernel(const float* __restrict__ Y,
                                     float* __restrict__ sums, int Ncols) {
    const int c = blockIdx.x;
    const int len = Ncols / gridDim.y;
    const float* row = Y + (size_t)c * Ncols + (size_t)blockIdx.y * len;
    float s = 0.0f, s2 = 0.0f;
    for (int i = threadIdx.x * 4; i < len; i += blockDim.x * 4) {
        float4 v = *(const float4*)(row + i);
        s += v.x + v.y + v.z + v.w;
        s2 += v.x * v.x + v.y * v.y + v.z * v.z + v.w * v.w;
    }
#pragma unroll
    for (int o = 16; o; o >>= 1) {
        s += __shfl_down_sync(0xFFFFFFFFu, s, o);
        s2 += __shfl_down_sync(0xFFFFFFFFu, s2, o);
    }
    __shared__ float ws[8], ws2[8];
    const int w = threadIdx.x >> 5, l = threadIdx.x & 31;
    if (l == 0) { ws[w] = s; ws2[w] = s2; }
    __syncthreads();
    if (threadIdx.x == 0) {
        float S = 0.0f, S2 = 0.0f;
        const int nw = blockDim.x >> 5;
        for (int i = 0; i < nw; ++i) { S += ws[i]; S2 += ws2[i]; }
        atomicAdd(&sums[c], S);
        atomicAdd(&sums[256 + c], S2);
    }
}

// ---------------------------------------------------------------------------
// BN apply + ReLU, in place on (C x Ncols); mean/rstd from raw sums
// ---------------------------------------------------------------------------
__global__ void bn_apply_ip_kernel(float* __restrict__ Y,
                                   const float* __restrict__ sums,
                                   const float* __restrict__ gamma,
                                   const float* __restrict__ beta,
                                   int Ncols, float invN) {
    size_t t = ((size_t)blockIdx.x * blockDim.x + threadIdx.x) * 4;
    const int c = (int)(t / Ncols);
    const float mean = sums[c] * invN;
    const float var = sums[256 + c] * invN - mean * mean;
    const float g = gamma[c] * rsqrtf(var + 1e-5f);
    const float b = beta[c] - mean * g;
    float4 v = *(float4*)(Y + t);
    v.x = fmaxf(v.x * g + b, 0.0f);
    v.y = fmaxf(v.y * g + b, 0.0f);
    v.z = fmaxf(v.z * g + b, 0.0f);
    v.w = fmaxf(v.w * g + b, 0.0f);
    *(float4*)(Y + t) = v;
}

// ---------------------------------------------------------------------------
// BN apply + ReLU, (C, B*N) -> out (B,C,N)
// ---------------------------------------------------------------------------
__global__ void bn_apply_out_kernel(const float* __restrict__ Y,
                                    const float* __restrict__ sums,
                                    const float* __restrict__ gamma,
                                    const float* __restrict__ beta,
                                    float* __restrict__ out,
                                    int B, int C, int N, float invN) {
    size_t t = ((size_t)blockIdx.x * blockDim.x + threadIdx.x) * 4;
    const int BN = B * N;
    const int c = (int)(t / BN);
    const int rem = (int)(t % BN);
    const int b = rem / N;
    const int n = rem % N;
    const float mean = sums[c] * invN;
    const float var = sums[256 + c] * invN - mean * mean;
    const float g = gamma[c] * rsqrtf(var + 1e-5f);
    const float bb = beta[c] - mean * g;
    float4 v = *(const float4*)(Y + t);
    v.x = fmaxf(v.x * g + bb, 0.0f);
    v.y = fmaxf(v.y * g + bb, 0.0f);
    v.z = fmaxf(v.z * g + bb, 0.0f);
    v.w = fmaxf(v.w * g + bb, 0.0f);
    *(float4*)(out + ((size_t)b * C + c) * N + n) = v;
}

// ---------------------------------------------------------------------------
// host driver
// ---------------------------------------------------------------------------
static inline void run_conv_bn_relu(const float* W, const float* X, float* Y,
                                    float* sums,
                                    const float* gamma, const float* beta,
                                    int M, int Ncols, int K, int bn_tile,
                                    bool apply_ip) {
    if (bn_tile == 64) {
        dim3 g(Ncols / 64, M / 128);
        sgemm_db_kernel<64, 2><<<g, 256>>>(W, X, Y, M, Ncols, K);
    } else {
        dim3 g(Ncols / 128, M / 128);
        sgemm_db_kernel<128, 4><<<g, 256>>>(W, X, Y, M, Ncols, K);
    }
    bn_stats_part_kernel<<<dim3(M, 8), 256>>>(Y, sums, Ncols);
    if (apply_ip) {
        int total = M * Ncols;
        bn_apply_ip_kernel<<<total / 1024, 256>>>(Y, sums, gamma, beta, Ncols,
                                                  1.0f / (float)Ncols);
    }
}

extern "C" void kernel_launch(void* const* d_in, const int* in_sizes, int n_in,
                              void* d_out, int out_size) {
    const float* in[26];
    for (int i = 0; i < 26 && i < n_in; ++i) in[i] = (const float*)d_in[i];

    const float *xyz0, *xyz1, *xyz2, *xyz3, *f0, *f1, *f2, *f3;
    if (in_sizes[1] == 8 * 64 * 8192) {  // interleaved: xyz0,f0,xyz1,f1,...
        xyz0 = in[0]; f0 = in[1]; xyz1 = in[2]; f1 = in[3];
        xyz2 = in[4]; f2 = in[5]; xyz3 = in[6]; f3 = in[7];
    } else {  // grouped
        xyz0 = in[0]; xyz1 = in[1]; xyz2 = in[2]; xyz3 = in[3];
        f0 = in[4]; f1 = in[5]; f2 = in[6]; f3 = in[7];
    }
    const float *w00 = in[8],  *g00 = in[9],  *b00 = in[10];
    const float *w01 = in[11], *g01 = in[12], *b01 = in[13];
    const float *w10 = in[14], *g10 = in[15], *b10 = in[16];
    const float *w11 = in[17], *g11 = in[18], *b11 = in[19];
    const float *w20 = in[20], *g20 = in[21], *b20 = in[22];
    const float *w21 = in[23], *g21 = in[24], *b21 = in[25];

    float *big, *Y00, *X2, *Y20, *F2N, *X1, *Y10, *F1N, *sums;
    cudaGetSymbolAddress((void**)&big, g_big);
    cudaGetSymbolAddress((void**)&Y00, g_Y00);
    cudaGetSymbolAddress((void**)&X2, g_X2);
    cudaGetSymbolAddress((void**)&Y20, g_Y20);
    cudaGetSymbolAddress((void**)&F2N, g_F2N);
    cudaGetSymbolAddress((void**)&X1, g_X1);
    cudaGetSymbolAddress((void**)&Y10, g_Y10);
    cudaGetSymbolAddress((void**)&F1N, g_F1N);
    cudaGetSymbolAddress((void**)&sums, g_sums);

    float* X0  = big;   // 192 x 65536 during FP0 concat + conv0
    float* Y01 = big;   // 128 x 65536 after conv0 (X0 dead: conv1 reads Y00)

    float* out = (float*)d_out;
    const int B = B_SZ;

    zero_sums_kernel<<<12, 256>>>(sums);

    // ---------------- FP2: xyz2 (n=512) <- xyz3 (m=128) ----------------
    {
        const int n = N2, m = N3, Cskip = 256, Cf = 512, cols = B * n;
        copy_skip_kernel<<<(B * Cskip * n) / 1024, 256>>>(f2, X2, B, Cskip, n);
        knn_interp_kernel<<<dim3(n / 256, B), 256>>>(
            xyz2, xyz3, f3, X2, n, m, Cf, Cskip, /*fb=*/Cf * m, /*fc=*/m, B);
        run_conv_bn_relu(w20, X2, Y20, sums + 0 * 512, g20, b20,
                         256, cols, 768, 64, true);
        run_conv_bn_relu(w21, Y20, F2N, sums + 1 * 512, g21, b21,
                         256, cols, 256, 64, true);
    }

    // ---------------- FP1: xyz1 (n=2048) <- xyz2 (m=512) ----------------
    {
        const int n = N1, m = N2, Cskip = 128, Cf = 256, cols = B * n;
        copy_skip_kernel<<<(B * Cskip * n) / 1024, 256>>>(f1, X1, B, Cskip, n);
        knn_interp_kernel<<<dim3(n / 256, B), 256>>>(
            xyz1, xyz2, F2N, X1, n, m, Cf, Cskip, /*fb=*/m, /*fc=*/B * m, B);
        run_conv_bn_relu(w10, X1, Y10, sums + 2 * 512, g10, b10,
                         256, cols, 384, 128, true);
        run_conv_bn_relu(w11, Y10, F1N, sums + 3 * 512, g11, b11,
                         128, cols, 256, 128, true);
    }

    // ---------------- FP0: xyz0 (n=8192) <- xyz1 (m=2048) ----------------
    {
        const int n = N0, m = N1, Cskip = 64, Cf = 128, cols = B * n;
        copy_skip_kernel<<<(B * Cskip * n) / 1024, 256>>>(f0, X0, B, Cskip, n);
        knn_interp_kernel<<<dim3(n / 256, B), 256>>>(
            xyz0, xyz1, F1N, X0, n, m, Cf, Cskip, /*fb=*/m, /*fc=*/B * m, B);
        run_conv_bn_relu(w00, X0, Y00, sums + 4 * 512, g00, b00,
                         128, cols, 192, 128, true);
        run_conv_bn_relu(w01, Y00, Y01, sums + 5 * 512, g01, b01,
                         128, cols, 128, 128, false);
        const int total = 128 * cols;
        bn_apply_out_kernel<<<total / 1024, 256>>>(Y01, sums + 5 * 512, g01,
                                                   b01, out, B, 128, n,
                                                   1.0f / (float)cols);
    }
}

// round 17
// speedup vs baseline: 1.1743x; 1.1560x over previous
#include <cuda_runtime.h>
#include <cstdint>

// ---------------------------------------------------------------------------
// PointNet++ decoder, round 17 layout:
//  * GEMMs: single-buffered f32x2 (FFMA2) SIMT kernels, tile shapes chosen so
//    every GEMM grid >= 256 CTAs (fixes the occ=12% latency starvation that
//    ncu showed for the 128-CTA FP2 grids).
//  * BN stats fused into the GEMM epilogue (atomicAdd of per-channel sums).
//  * BN apply + ReLU fused into consumers: conv1 applies while staging its
//    B tile; interp applies while gathering. finalize_gb turns raw sums into
//    per-channel (scale, bias) once per layer.
// Target sm_100 (no 'a'): no tcgen05 / kind::tf32.
// ---------------------------------------------------------------------------

#define B_SZ 8
#define N0 8192
#define N1 2048
#define N2 512
#define N3 128

__device__ float g_big[192 * (B_SZ * N0)];   // X0; later aliased as Y01
__device__ float g_Y00[128 * (B_SZ * N0)];
__device__ float g_X2[768 * (B_SZ * N2)];
__device__ float g_Y20[256 * (B_SZ * N2)];
__device__ float g_F2N[256 * (B_SZ * N2)];
__device__ float g_X1[384 * (B_SZ * N1)];
__device__ float g_Y10[256 * (B_SZ * N1)];
__device__ float g_F1N[128 * (B_SZ * N1)];
__device__ float g_sums[6 * 512];  // per layer: [0,256)=sum, [256,512)=sumsq
__device__ float g_gb[6 * 512];    // per layer: gb[2c]=scale, gb[2c+1]=bias

// ---------------- packed f32x2 helpers ----------------
__device__ __forceinline__ unsigned long long pack2(float x, float y) {
    unsigned long long r;
    asm("mov.b64 %0, {%1, %2};" : "=l"(r) : "f"(x), "f"(y));
    return r;
}
__device__ __forceinline__ unsigned long long fma2(unsigned long long a,
                                                   unsigned long long b,
                                                   unsigned long long c) {
    unsigned long long d;
    asm("fma.rn.f32x2 %0, %1, %2, %3;" : "=l"(d) : "l"(a), "l"(b), "l"(c));
    return d;
}
__device__ __forceinline__ void unpack2(unsigned long long v,
                                        float& lo, float& hi) {
    asm("mov.b64 {%0, %1}, %2;" : "=f"(lo), "=f"(hi) : "l"(v));
}

// ---------------------------------------------------------------------------
// copy skip features (B,C,N) -> X rows [0,C), layout (C, B*N)
// ---------------------------------------------------------------------------
__global__ void copy_skip_kernel(const float* __restrict__ src,
                                 float* __restrict__ dst,
                                 int B, int C, int N) {
    size_t t = ((size_t)blockIdx.x * blockDim.x + threadIdx.x) * 4;
    int BN = B * N;
    int c = (int)(t / BN);
    int rem = (int)(t % BN);
    int b = rem / N;
    int n = rem % N;
    *(float4*)(dst + t) =
        *(const float4*)(src + ((size_t)b * C + c) * N + n);
}

// ---------------------------------------------------------------------------
// kNN(3) + inverse-distance interpolation (channel-major feats).
// If gb != nullptr, each gathered feature gets BN+ReLU: max(f*g + b, 0).
// ---------------------------------------------------------------------------
__global__ void knn_interp_kernel(const float* __restrict__ uxyz,
                                  const float* __restrict__ kxyz,
                                  const float* __restrict__ feats,
                                  const float* __restrict__ gb,
                                  float* __restrict__ X,
                                  int n, int m, int C, int c0,
                                  int fb, int fc, int B) {
    __shared__ float skx[2048];
    __shared__ float sky[2048];
    __shared__ float skz[2048];

    const int b = blockIdx.y;
    const int pi = blockIdx.x * blockDim.x + threadIdx.x;

    for (int j = threadIdx.x; j < m; j += blockDim.x) {
        const float* p = kxyz + ((size_t)b * m + j) * 3;
        skx[j] = p[0];
        sky[j] = p[1];
        skz[j] = p[2];
    }
    __syncthreads();
    if (pi >= n) return;

    const float* up = uxyz + ((size_t)b * n + pi) * 3;
    const float ux = up[0], uy = up[1], uz = up[2];

    float d0 = 1e30f, d1 = 1e30f, d2 = 1e30f;
    int i0 = 0, i1 = 0, i2 = 0;
    for (int j = 0; j < m; ++j) {
        float dx = ux - skx[j];
        float dy = uy - sky[j];
        float dz = uz - skz[j];
        float d = dx * dx + dy * dy + dz * dz;
        if (d < d2) {
            if (d < d1) {
                d2 = d1; i2 = i1;
                if (d < d0) { d1 = d0; i1 = i0; d0 = d; i0 = j; }
                else        { d1 = d;  i1 = j; }
            } else {
                d2 = d; i2 = j;
            }
        }
    }

    float r0 = 1.0f / (d0 + 1e-8f);
    float r1 = 1.0f / (d1 + 1e-8f);
    float r2 = 1.0f / (d2 + 1e-8f);
    float rs = 1.0f / (r0 + r1 + r2);
    const float w0 = r0 * rs, w1 = r1 * rs, w2 = r2 * rs;

    const float* fbase = feats + (size_t)b * fb;
    const size_t ocol = (size_t)b * n + pi;
    const size_t rowstride = (size_t)B * n;
    float* outp = X + (size_t)c0 * rowstride + ocol;
    if (gb) {
        for (int c = 0; c < C; ++c) {
            const float* fr = fbase + (size_t)c * fc;
            const float g = gb[2 * c], bb = gb[2 * c + 1];
            float a0 = fmaxf(fr[i0] * g + bb, 0.0f);
            float a1 = fmaxf(fr[i1] * g + bb, 0.0f);
            float a2 = fmaxf(fr[i2] * g + bb, 0.0f);
            outp[(size_t)c * rowstride] = w0 * a0 + w1 * a1 + w2 * a2;
        }
    } else {
        for (int c = 0; c < C; ++c) {
            const float* fr = fbase + (size_t)c * fc;
            outp[(size_t)c * rowstride] =
                w0 * fr[i0] + w1 * fr[i1] + w2 * fr[i2];
        }
    }
}

// ---------------------------------------------------------------------------
// Fused SGEMM (f32x2) + BN-stat epilogue (+ optional BN apply on B load).
// C(M x N) = A(M x K) @ apply(B)(K x N), row-major.
// Tile: BM=RM*16 rows x BN=NP*32 cols, 256 threads (16x16), micro RM x 2*NP.
// APPLY: B elements get max(b*g + bias, 0) with per-channel (g, bias) from
// gb (channel = global k row). Epilogue: atomicAdd per-channel {sum, sumsq}.
// M in {128,256}; N % BN == 0; K % 16 == 0 (exact for this problem).
// ---------------------------------------------------------------------------
template <int RM, int NP, bool APPLY>
__global__ __launch_bounds__(256, 3) void gemm_fused_kernel(
    const float* __restrict__ A, const float* __restrict__ Bm,
    float* __restrict__ C, float* __restrict__ sums,
    const float* __restrict__ gb, int M, int N, int K) {
    constexpr int BM = RM * 16;
    constexpr int BN = NP * 32;
    __shared__ float As[16][BM];  // As[k][m]
    __shared__ float Bs[16][BN];  // Bs[k][n]

    const int tid = threadIdx.x;
    const int bm = blockIdx.y * BM;
    const int bn = blockIdx.x * BN;
    const int tx = tid & 15;
    const int ty = tid >> 4;

    // ---- A loader mapping ----
    int a_row, a_c0;
    if (BM == 128) { a_row = tid & 127; a_c0 = (tid >> 7) * 4; }
    else           { a_row = tid & 63;  a_c0 = (tid >> 6) * 4; }
    const float* Ap0 = A + (size_t)(bm + a_row) * K + a_c0;
    const float* Ap1 = Ap0 + 8;  // only used when BM == 128

    // ---- B loader mapping ----
    int b_k0, b_col;
    if (BN == 128) { b_k0 = tid >> 5; b_col = (tid & 31) * 4; }
    else           { b_k0 = tid >> 4; b_col = (tid & 15) * 4; }
    const float* Bp0 = Bm + (size_t)b_k0 * N + bn + b_col;
    const float* Bp1 = Bp0 + (size_t)8 * N;  // only when BN == 128

    unsigned long long acc[RM][NP];
#pragma unroll
    for (int i = 0; i < RM; ++i)
#pragma unroll
        for (int j = 0; j < NP; ++j) acc[i][j] = 0ull;

    // ---- prologue: fetch tile 0 (apply BN to B if requested) ----
    float4 pa0 = *(const float4*)(Ap0);
    float4 pa1;
    if (BM == 128) pa1 = *(const float4*)(Ap1);
    float4 pb0 = *(const float4*)(Bp0);
    float4 pb1;
    if (BN == 128) pb1 = *(const float4*)(Bp1);
    if (APPLY) {
        float g0 = gb[2 * b_k0], s0 = gb[2 * b_k0 + 1];
        pb0.x = fmaxf(pb0.x * g0 + s0, 0.0f);
        pb0.y = fmaxf(pb0.y * g0 + s0, 0.0f);
        pb0.z = fmaxf(pb0.z * g0 + s0, 0.0f);
        pb0.w = fmaxf(pb0.w * g0 + s0, 0.0f);
        if (BN == 128) {
            float g1 = gb[2 * (b_k0 + 8)], s1 = gb[2 * (b_k0 + 8) + 1];
            pb1.x = fmaxf(pb1.x * g1 + s1, 0.0f);
            pb1.y = fmaxf(pb1.y * g1 + s1, 0.0f);
            pb1.z = fmaxf(pb1.z * g1 + s1, 0.0f);
            pb1.w = fmaxf(pb1.w * g1 + s1, 0.0f);
        }
    }

    for (int k0 = 0; k0 < K; k0 += 16) {
        // store prefetched tile
        As[a_c0 + 0][a_row] = pa0.x;
        As[a_c0 + 1][a_row] = pa0.y;
        As[a_c0 + 2][a_row] = pa0.z;
        As[a_c0 + 3][a_row] = pa0.w;
        if (BM == 128) {
            As[a_c0 + 8][a_row] = pa1.x;
            As[a_c0 + 9][a_row] = pa1.y;
            As[a_c0 + 10][a_row] = pa1.z;
            As[a_c0 + 11][a_row] = pa1.w;
        }
        *(float4*)&Bs[b_k0][b_col] = pb0;
        if (BN == 128) *(float4*)&Bs[b_k0 + 8][b_col] = pb1;
        __syncthreads();

        // prefetch next tile
        if (k0 + 16 < K) {
            const int ko = k0 + 16;
            pa0 = *(const float4*)(Ap0 + ko);
            if (BM == 128) pa1 = *(const float4*)(Ap1 + ko);
            pb0 = *(const float4*)(Bp0 + (size_t)ko * N);
            if (BN == 128) pb1 = *(const float4*)(Bp1 + (size_t)ko * N);
            if (APPLY) {
                const int c0ch = ko + b_k0;
                float g0 = gb[2 * c0ch], s0 = gb[2 * c0ch + 1];
                pb0.x = fmaxf(pb0.x * g0 + s0, 0.0f);
                pb0.y = fmaxf(pb0.y * g0 + s0, 0.0f);
                pb0.z = fmaxf(pb0.z * g0 + s0, 0.0f);
                pb0.w = fmaxf(pb0.w * g0 + s0, 0.0f);
                if (BN == 128) {
                    float g1 = gb[2 * (c0ch + 8)], s1 = gb[2 * (c0ch + 8) + 1];
                    pb1.x = fmaxf(pb1.x * g1 + s1, 0.0f);
                    pb1.y = fmaxf(pb1.y * g1 + s1, 0.0f);
                    pb1.z = fmaxf(pb1.z * g1 + s1, 0.0f);
                    pb1.w = fmaxf(pb1.w * g1 + s1, 0.0f);
                }
            }
        }

#pragma unroll
        for (int kk = 0; kk < 16; ++kk) {
            float af[RM];
            *(float4*)&af[0] = *(const float4*)&As[kk][ty * 4];
            if (RM == 8)
                *(float4*)&af[4] = *(const float4*)&As[kk][ty * 4 + 64];
            unsigned long long bp[NP];
            {
                ulonglong2 t0 = *(const ulonglong2*)&Bs[kk][tx * 4];
                bp[0] = t0.x; bp[1] = t0.y;
                if (NP == 4) {
                    ulonglong2 t1 = *(const ulonglong2*)&Bs[kk][tx * 4 + 64];
                    bp[2] = t1.x; bp[3] = t1.y;
                }
            }
#pragma unroll
            for (int i = 0; i < RM; ++i) {
                unsigned long long aa = pack2(af[i], af[i]);
#pragma unroll
                for (int j = 0; j < NP; ++j)
                    acc[i][j] = fma2(aa, bp[j], acc[i][j]);
            }
        }
        __syncthreads();
    }

    // ---- epilogue: write C + fused BN stats ----
#pragma unroll
    for (int ih = 0; ih < RM / 4; ++ih) {
#pragma unroll
        for (int i = 0; i < 4; ++i) {
            const int row = bm + ih * 64 + ty * 4 + i;
            float* cp = C + (size_t)row * N + bn;
            float v[NP * 2];
#pragma unroll
            for (int j = 0; j < NP; ++j)
                unpack2(acc[ih * 4 + i][j], v[2 * j], v[2 * j + 1]);
            *(float4*)(cp + tx * 4) = make_float4(v[0], v[1], v[2], v[3]);
            if (NP == 4)
                *(float4*)(cp + tx * 4 + 64) =
                    make_float4(v[4], v[5], v[6], v[7]);

            // per-row partial stats over this thread's columns
            float s = 0.0f, q = 0.0f;
#pragma unroll
            for (int j = 0; j < NP * 2; ++j) {
                s += v[j];
                q += v[j] * v[j];
            }
            // butterfly over the 16 tx lanes (halves of the warp stay apart)
#pragma unroll
            for (int o = 1; o < 16; o <<= 1) {
                s += __shfl_xor_sync(0xFFFFFFFFu, s, o);
                q += __shfl_xor_sync(0xFFFFFFFFu, q, o);
            }
            if (tx == 0) {
                atomicAdd(&sums[row], s);
                atomicAdd(&sums[256 + row], q);
            }
        }
    }
}

// ---------------------------------------------------------------------------
// zero sums
// ---------------------------------------------------------------------------
__global__ void zero_sums_kernel(float* sums) {
    sums[blockIdx.x * 256 + threadIdx.x] = 0.0f;
}

// ---------------------------------------------------------------------------
// finalize: raw {sum, sumsq} -> per-channel (scale, bias)
// ---------------------------------------------------------------------------
__global__ void finalize_gb_kernel(const float* __restrict__ sums,
                                   const float* __restrict__ gamma,
                                   const float* __restrict__ beta,
                                   float* __restrict__ gb,
                                   int C, float invN) {
    const int c = threadIdx.x;
    if (c < C) {
        const float mean = sums[c] * invN;
        const float var = sums[256 + c] * invN - mean * mean;
        const float g = gamma[c] * rsqrtf(var + 1e-5f);
        gb[2 * c] = g;
        gb[2 * c + 1] = beta[c] - mean * g;
    }
}

// ---------------------------------------------------------------------------
// final: BN apply + ReLU, (C, B*N) -> out (B,C,N), using gb
// ---------------------------------------------------------------------------
__global__ void bn_apply_out_kernel(const float* __restrict__ Y,
                                    const float* __restrict__ gb,
                                    float* __restrict__ out,
                                    int B, int C, int N) {
    size_t t = ((size_t)blockIdx.x * blockDim.x + threadIdx.x) * 4;
    const int BN = B * N;
    const int c = (int)(t / BN);
    const int rem = (int)(t % BN);
    const int b = rem / N;
    const int n = rem % N;
    const float g = gb[2 * c], bb = gb[2 * c + 1];
    float4 v = *(const float4*)(Y + t);
    v.x = fmaxf(v.x * g + bb, 0.0f);
    v.y = fmaxf(v.y * g + bb, 0.0f);
    v.z = fmaxf(v.z * g + bb, 0.0f);
    v.w = fmaxf(v.w * g + bb, 0.0f);
    *(float4*)(out + ((size_t)b * C + c) * N + n) = v;
}

// ---------------------------------------------------------------------------
// host driver
// ---------------------------------------------------------------------------
extern "C" void kernel_launch(void* const* d_in, const int* in_sizes, int n_in,
                              void* d_out, int out_size) {
    const float* in[26];
    for (int i = 0; i < 26 && i < n_in; ++i) in[i] = (const float*)d_in[i];

    const float *xyz0, *xyz1, *xyz2, *xyz3, *f0, *f1, *f2, *f3;
    if (in_sizes[1] == 8 * 64 * 8192) {  // interleaved: xyz0,f0,xyz1,f1,...
        xyz0 = in[0]; f0 = in[1]; xyz1 = in[2]; f1 = in[3];
        xyz2 = in[4]; f2 = in[5]; xyz3 = in[6]; f3 = in[7];
    } else {  // grouped
        xyz0 = in[0]; xyz1 = in[1]; xyz2 = in[2]; xyz3 = in[3];
        f0 = in[4]; f1 = in[5]; f2 = in[6]; f3 = in[7];
    }
    const float *w00 = in[8],  *g00 = in[9],  *b00 = in[10];
    const float *w01 = in[11], *g01 = in[12], *b01 = in[13];
    const float *w10 = in[14], *g10 = in[15], *b10 = in[16];
    const float *w11 = in[17], *g11 = in[18], *b11 = in[19];
    const float *w20 = in[20], *g20 = in[21], *b20 = in[22];
    const float *w21 = in[23], *g21 = in[24], *b21 = in[25];

    float *big, *Y00, *X2, *Y20, *F2N, *X1, *Y10, *F1N, *sums, *gbb;
    cudaGetSymbolAddress((void**)&big, g_big);
    cudaGetSymbolAddress((void**)&Y00, g_Y00);
    cudaGetSymbolAddress((void**)&X2, g_X2);
    cudaGetSymbolAddress((void**)&Y20, g_Y20);
    cudaGetSymbolAddress((void**)&F2N, g_F2N);
    cudaGetSymbolAddress((void**)&X1, g_X1);
    cudaGetSymbolAddress((void**)&Y10, g_Y10);
    cudaGetSymbolAddress((void**)&F1N, g_F1N);
    cudaGetSymbolAddress((void**)&sums, g_sums);
    cudaGetSymbolAddress((void**)&gbb, g_gb);

    float* X0  = big;   // 192 x 65536 during FP0 concat + conv0
    float* Y01 = big;   // 128 x 65536 after conv0 (X0 dead: conv1 reads Y00)

    float* out = (float*)d_out;
    const int B = B_SZ;

    zero_sums_kernel<<<12, 256>>>(sums);

    // ---------------- FP2: xyz2 (n=512) <- xyz3 (m=128) ----------------
    {
        const int n = N2, m = N3, Cskip = 256, Cf = 512, cols = B * n;  // 4096
        copy_skip_kernel<<<(B * Cskip * n) / 1024, 256>>>(f2, X2, B, Cskip, n);
        knn_interp_kernel<<<dim3(n / 256, B), 256>>>(
            xyz2, xyz3, f3, nullptr, X2, n, m, Cf, Cskip,
            /*fb=*/Cf * m, /*fc=*/m, B);

        // conv0: M=256, N=4096, K=768 | 64x64 tiles -> grid 64x4 = 256
        gemm_fused_kernel<4, 2, false><<<dim3(cols / 64, 4), 256>>>(
            w20, X2, Y20, sums + 0 * 512, nullptr, 256, cols, 768);
        finalize_gb_kernel<<<1, 256>>>(sums + 0 * 512, g20, b20, gbb + 0 * 512,
                                       256, 1.0f / (float)cols);

        // conv1: M=256, N=4096, K=256 | apply gb0 on B | grid 256
        gemm_fused_kernel<4, 2, true><<<dim3(cols / 64, 4), 256>>>(
            w21, Y20, F2N, sums + 1 * 512, gbb + 0 * 512, 256, cols, 256);
        finalize_gb_kernel<<<1, 256>>>(sums + 1 * 512, g21, b21, gbb + 1 * 512,
                                       256, 1.0f / (float)cols);
    }

    // ---------------- FP1: xyz1 (n=2048) <- xyz2 (m=512) ----------------
    {
        const int n = N1, m = N2, Cskip = 128, Cf = 256, cols = B * n;  // 16384
        copy_skip_kernel<<<(B * Cskip * n) / 1024, 256>>>(f1, X1, B, Cskip, n);
        // interp gathers RAW F2N and applies gb1 inline
        knn_interp_kernel<<<dim3(n / 256, B), 256>>>(
            xyz1, xyz2, F2N, gbb + 1 * 512, X1, n, m, Cf, Cskip,
            /*fb=*/m, /*fc=*/B * m, B);

        // conv0: M=256, N=16384, K=384 | 128x128 tiles -> grid 128x2 = 256
        gemm_fused_kernel<8, 4, false><<<dim3(cols / 128, 2), 256>>>(
            w10, X1, Y10, sums + 2 * 512, nullptr, 256, cols, 384);
        finalize_gb_kernel<<<1, 256>>>(sums + 2 * 512, g10, b10, gbb + 2 * 512,
                                       256, 1.0f / (float)cols);

        // conv1: M=128, N=16384, K=256 | 64x128 tiles -> grid 128x2 = 256
        gemm_fused_kernel<4, 4, true><<<dim3(cols / 128, 2), 256>>>(
            w11, Y10, F1N, sums + 3 * 512, gbb + 2 * 512, 128, cols, 256);
        finalize_gb_kernel<<<1, 256>>>(sums + 3 * 512, g11, b11, gbb + 3 * 512,
                                       128, 1.0f / (float)cols);
    }

    // ---------------- FP0: xyz0 (n=8192) <- xyz1 (m=2048) ----------------
    {
        const int n = N0, m = N1, Cskip = 64, Cf = 128, cols = B * n;  // 65536
        copy_skip_kernel<<<(B * Cskip * n) / 1024, 256>>>(f0, X0, B, Cskip, n);
        // interp gathers RAW F1N and applies gb3 inline
        knn_interp_kernel<<<dim3(n / 256, B), 256>>>(
            xyz0, xyz1, F1N, gbb + 3 * 512, X0, n, m, Cf, Cskip,
            /*fb=*/m, /*fc=*/B * m, B);

        // conv0: M=128, N=65536, K=192 | 128x128 tiles -> grid 512x1
        gemm_fused_kernel<8, 4, false><<<dim3(cols / 128, 1), 256>>>(
            w00, X0, Y00, sums + 4 * 512, nullptr, 128, cols, 192);
        finalize_gb_kernel<<<1, 256>>>(sums + 4 * 512, g00, b00, gbb + 4 * 512,
                                       128, 1.0f / (float)cols);

        // conv1: M=128, N=65536, K=128 | apply gb4 on B | grid 512x1
        gemm_fused_kernel<8, 4, true><<<dim3(cols / 128, 1), 256>>>(
            w01, Y00, Y01, sums + 5 * 512, gbb + 4 * 512, 128, cols, 128);
        finalize_gb_kernel<<<1, 256>>>(sums + 5 * 512, g01, b01, gbb + 5 * 512,
                                       128, 1.0f / (float)cols);

        bn_apply_out_kernel<<<128 * cols / 1024, 256>>>(
            Y01, gbb + 5 * 512, out, B, 128, n);
    }
}